// round 10
// baseline (speedup 1.0000x reference)
#include <cuda_runtime.h>
#include <cuda_bf16.h>
#include <math.h>

// ---------------- problem constants ------------------------------------------
#define NQ      64
#define KDIM    768
#define KW      (KDIM / 4)          // 192 int32 words per row
#define TILE_M  128                 // bank rows per CTA tile
#define CHUNK_K 64                  // fp32 elems per chunk per row (16 words)
#define NCHUNK  (KDIM / CHUNK_K)    // 12
#define MAXROWS 500000
#define NSEG    8                   // top-k segments per query
#define SEGK    16                  // candidates kept per (q, segment)
#define CAND    32                  // candidates exactly rescored per query
#define TB_PAD  136                 // transpose buffer row pitch (bf16 elems)
#define QSCALE  (127.0f / 6.5f)     // bank int8 quantization (fixed scale)
#define SBANK   (6.5f / 127.0f)

// ---------------- smem layout (score kernel) ---------------------------------
#define SM_INVN 0                                   // float[128]
#define SM_SQ   512                                 // float[64]
#define SM_Q8   1024                                // int[192][64] = 49152 B (reused as TB)
#define SM_B8   (SM_Q8 + KW * NQ * 4)               // 50176: int[16][128] = 8192 B
#define SCORE_SMEM (SM_B8 + 16 * 128 * 4)           // 58368

// ---------------- device scratch (allocation-free rule) ----------------------
__device__ __align__(16) float g_qn [NQ * KDIM];                     // fp32 normalized queries
__device__ __align__(16) int   g_q8 [NQ * KW];                       // int8-packed queries
__device__                float g_qsc[NQ];                           // per-query quant scale
__device__ __align__(16) __nv_bfloat16 g_simsb[(size_t)NQ * MAXROWS]; // 64 MB bf16 sims
__device__ float g_segv[NQ * NSEG * SEGK];
__device__ int   g_segi[NQ * NSEG * SEGK];

// ---------------- helpers -----------------------------------------------------
__device__ __forceinline__ int pack4(int v0, int v1, int v2, int v3) {
    int b01 = __byte_perm(v0, v1, 0x0040);
    int b23 = __byte_perm(v2, v3, 0x0040);
    return __byte_perm(b01, b23, 0x5410);
}
__device__ __forceinline__ int quant1(float f) {
    return __float2int_rn(fminf(fmaxf(f * QSCALE, -127.f), 127.f));
}

// ---------------- kernel 1: normalize + quantize queries ---------------------
__global__ void norm_q_kernel(const float* __restrict__ q) {
    __shared__ float reds[256], redm[256];
    const int qi = blockIdx.x, tid = threadIdx.x;
    float4 f = make_float4(0.f, 0.f, 0.f, 0.f);
    if (tid < KW) f = *(const float4*)(q + qi * KDIM + tid * 4);
    float ss = f.x * f.x + f.y * f.y + f.z * f.z + f.w * f.w;
    float mx = fmaxf(fmaxf(fabsf(f.x), fabsf(f.y)), fmaxf(fabsf(f.z), fabsf(f.w)));
    reds[tid] = ss; redm[tid] = mx;
    __syncthreads();
    for (int st = 128; st > 0; st >>= 1) {
        if (tid < st) {
            reds[tid] += reds[tid + st];
            redm[tid] = fmaxf(redm[tid], redm[tid + st]);
        }
        __syncthreads();
    }
    const float inv = 1.0f / fmaxf(sqrtf(reds[0]), 1e-12f);
    const float sq  = fmaxf(redm[0] * inv, 1e-30f) / 127.0f;
    if (tid < KW) {
        float4 o = make_float4(f.x * inv, f.y * inv, f.z * inv, f.w * inv);
        *(float4*)(g_qn + qi * KDIM + tid * 4) = o;
        const float r = 1.0f / sq;
        g_q8[qi * KW + tid] = pack4(
            __float2int_rn(fminf(fmaxf(o.x * r, -127.f), 127.f)),
            __float2int_rn(fminf(fmaxf(o.y * r, -127.f), 127.f)),
            __float2int_rn(fminf(fmaxf(o.z * r, -127.f), 127.f)),
            __float2int_rn(fminf(fmaxf(o.w * r, -127.f), 127.f)));
    }
    if (tid == 0) g_qsc[qi] = sq;
}

// ---------------- kernel 2: int8 dp4a score ----------------------------------
__device__ __forceinline__ void ld_chunk(float4 (&f)[8], const float* const (&rp)[8],
                                         const bool (&vld)[8], int c) {
    #pragma unroll
    for (int p = 0; p < 8; p++) {
        if (vld[p]) f[p] = *(const float4*)(rp[p] + c * CHUNK_K);
        else        f[p] = make_float4(0.f, 0.f, 0.f, 0.f);
    }
}

__global__ __launch_bounds__(256, 2)
void score_kernel(const float* __restrict__ bank, int nrows) {
    extern __shared__ char smem[];
    int*   qsm  = (int*)(smem + SM_Q8);
    int*   bsm  = (int*)(smem + SM_B8);
    float* invn = (float*)(smem + SM_INVN);
    float* sqs  = (float*)(smem + SM_SQ);
    const int tid = threadIdx.x, warp = tid >> 5, lane = tid & 31;
    const int lr = lane >> 4, lc = lane & 15;

    // ---- global load mapping: 16 lanes per row, line-contiguous LDG.128 ------
    int rloc[8]; const float* rp[8]; bool vld[8]; float ssq[8];
    #pragma unroll
    for (int p = 0; p < 8; p++) {
        int r = p * 16 + warp * 2 + lr;
        rloc[p] = r;
        long long grow = (long long)blockIdx.x * TILE_M + r;
        vld[p] = grow < (long long)nrows;
        rp[p]  = bank + grow * (long long)KDIM + lc * 4;
        ssq[p] = 0.f;
    }
    const int bidx = (lc << 7);                       // lc*128 (word index base)
    const int bswz = (lc & 7) << 2;                   // XOR swizzle for this lane's kw

    // ---- stage queries (int8 words, transposed [kw][64]) + scales ------------
    for (int i = tid; i < NQ * KW; i += 256) {
        int qi = i / KW, kw = i - qi * KW;
        qsm[kw * NQ + qi] = g_q8[i];
    }
    if (tid < NQ) sqs[tid] = g_qsc[tid];

    // ---- output mapping: 8 q x 4 rows per thread ------------------------------
    const int q0 = (tid & 7) * 8;
    const int r0 = (tid >> 3) * 4;

    int acc[8][4];
    #pragma unroll
    for (int i = 0; i < 8; i++)
        #pragma unroll
        for (int j = 0; j < 4; j++) acc[i][j] = 0;

    float4 f[8];
    ld_chunk(f, rp, vld, 0);             // prologue: chunk 0 in flight

    for (int c = 0; c < NCHUNK; c++) {
        // convert + quantize + STS chunk c (consumes f[], waits on its LDGs)
        #pragma unroll
        for (int p = 0; p < 8; p++) {
            float4 fv = f[p];
            ssq[p] += fv.x * fv.x + fv.y * fv.y + fv.z * fv.z + fv.w * fv.w;
            int w = pack4(quant1(fv.x), quant1(fv.y), quant1(fv.z), quant1(fv.w));
            bsm[bidx + (rloc[p] ^ bswz)] = w;
        }
        __syncthreads();

        // next chunk's loads issued before compute (latency hidden behind dp4a)
        if (c + 1 < NCHUNK) ld_chunk(f, rp, vld, c + 1);

        // dp4a over chunk c: 16 K-words x (8 q x 4 rows)
        #pragma unroll 4
        for (int kl = 0; kl < 16; kl++) {
            const int kw = c * 16 + kl;
            int4 qa = *(const int4*)&qsm[kw * NQ + q0];
            int4 qb = *(const int4*)&qsm[kw * NQ + q0 + 4];
            int4 bw = *(const int4*)&bsm[(kl << 7) + (r0 ^ ((kl & 7) << 2))];
            int qw[8] = {qa.x, qa.y, qa.z, qa.w, qb.x, qb.y, qb.z, qb.w};
            int bv[4] = {bw.x, bw.y, bw.z, bw.w};
            #pragma unroll
            for (int i = 0; i < 8; i++)
                #pragma unroll
                for (int j = 0; j < 4; j++)
                    acc[i][j] = __dp4a(qw[i], bv[j], acc[i][j]);
        }
        __syncthreads();
    }

    // ---- row inverse norms (16 lanes share a row) -----------------------------
    #pragma unroll
    for (int p = 0; p < 8; p++) {
        float s = ssq[p];
        s += __shfl_xor_sync(0xffffffffu, s, 1);
        s += __shfl_xor_sync(0xffffffffu, s, 2);
        s += __shfl_xor_sync(0xffffffffu, s, 4);
        s += __shfl_xor_sync(0xffffffffu, s, 8);
        if (lc == 0) invn[rloc[p]] = 1.0f / fmaxf(sqrtf(s), 1e-12f);
    }
    __syncthreads();

    // ---- epilogue 1: screen values -> smem transpose buffer [q][TB_PAD] bf16 --
    // (overwrites qsm region; all qsm reads completed above)
    {
        __nv_bfloat16* tb = (__nv_bfloat16*)(smem + SM_Q8);
        const float i0 = invn[r0], i1 = invn[r0 + 1], i2 = invn[r0 + 2], i3 = invn[r0 + 3];
        #pragma unroll
        for (int i = 0; i < 8; i++) {
            const float qs = sqs[q0 + i] * SBANK;
            float s0 = (float)acc[i][0] * qs * i0;
            float s1 = (float)acc[i][1] * qs * i1;
            float s2 = (float)acc[i][2] * qs * i2;
            float s3 = (float)acc[i][3] * qs * i3;
            __nv_bfloat162 u01 = __floats2bfloat162_rn(s0, s1);
            __nv_bfloat162 u23 = __floats2bfloat162_rn(s2, s3);
            uint2 u;
            u.x = *(unsigned*)&u01;
            u.y = *(unsigned*)&u23;
            *(uint2*)&tb[(q0 + i) * TB_PAD + r0] = u;
        }
    }
    __syncthreads();

    // ---- epilogue 2: coalesced vectorized sims store --------------------------
    {
        const int q = tid >> 2, seg = tid & 3;
        const long long tb0 = (long long)blockIdx.x * TILE_M;
        const __nv_bfloat16* tb = (const __nv_bfloat16*)(smem + SM_Q8);
        __nv_bfloat16* dst = g_simsb + (size_t)q * nrows;
        if ((nrows & 7) == 0) {
            #pragma unroll
            for (int i = 0; i < 4; i++) {
                long long g0 = tb0 + seg * 32 + i * 8;
                if (g0 + 8 <= (long long)nrows) {
                    uint4 v = *(const uint4*)(smem + SM_Q8 + q * (TB_PAD * 2) + seg * 64 + i * 16);
                    *(uint4*)(dst + g0) = v;
                } else {
                    for (int e = 0; e < 8 && g0 + e < (long long)nrows; e++)
                        dst[g0 + e] = tb[q * TB_PAD + seg * 32 + i * 8 + e];
                }
            }
        } else {
            for (int i = 0; i < 32; i++) {
                long long g0 = tb0 + seg * 32 + i;
                if (g0 < (long long)nrows) dst[g0] = tb[q * TB_PAD + seg * 32 + i];
            }
        }
    }
}

// ---------------- kernel 3: segmented top-16 screening -----------------------
__device__ __forceinline__ void tk_insert(float (&v)[SEGK], int (&id)[SEGK],
                                          float nv, int ni) {
    if (nv <= v[SEGK - 1]) return;
    int j = SEGK - 1;
    while (j > 0 && nv > v[j - 1]) { v[j] = v[j - 1]; id[j] = id[j - 1]; j--; }
    v[j] = nv; id[j] = ni;
}

__global__ __launch_bounds__(256, 1) void topk_kernel(int nrows) {
    __shared__ float sv[256 * SEGK];
    __shared__ int   si[256 * SEGK];
    const int seg = blockIdx.x, q = blockIdx.y, tid = threadIdx.x;
    const int len  = ((nrows + NSEG - 1) / NSEG + 3) & ~3;
    const int base = seg * len;
    const int end  = min(base + len, nrows);
    const __nv_bfloat16* s = g_simsb + (size_t)q * nrows;

    float vals[SEGK]; int ids[SEGK];
    #pragma unroll
    for (int i = 0; i < SEGK; i++) { vals[i] = -3.4e38f; ids[i] = 0x7fffffff; }

    if ((nrows & 3) == 0 && base < end) {
        const uint2* s4 = (const uint2*)s;
        for (int i = (base >> 2) + tid; i < (end >> 2); i += 256) {
            uint2 u = s4[i];
            __nv_bfloat162 p0 = *(__nv_bfloat162*)&u.x;
            __nv_bfloat162 p1 = *(__nv_bfloat162*)&u.y;
            int bi = i << 2;
            tk_insert(vals, ids, __low2float(p0),  bi);
            tk_insert(vals, ids, __high2float(p0), bi + 1);
            tk_insert(vals, ids, __low2float(p1),  bi + 2);
            tk_insert(vals, ids, __high2float(p1), bi + 3);
        }
    } else {
        for (int i = base + tid; i < end; i += 256)
            tk_insert(vals, ids, __bfloat162float(s[i]), i);
    }

    #pragma unroll
    for (int i = 0; i < SEGK; i++) { sv[tid * SEGK + i] = vals[i]; si[tid * SEGK + i] = ids[i]; }
    __syncthreads();

    for (int st = 128; st > 0; st >>= 1) {
        if (tid < st) {
            const int ao = tid * SEGK, bo = (tid + st) * SEGK;
            float ov[SEGK]; int oi[SEGK];
            int ia = 0, ib = 0;
            #pragma unroll
            for (int o = 0; o < SEGK; o++) {
                float va = (ia < SEGK) ? sv[ao + ia] : -3.4e38f;
                float vb = (ib < SEGK) ? sv[bo + ib] : -3.4e38f;
                bool takeA;
                if (va > vb) takeA = true;
                else if (va < vb) takeA = false;
                else takeA = (si[ao + min(ia, SEGK - 1)] <= si[bo + min(ib, SEGK - 1)]);
                if (takeA) { ov[o] = va; oi[o] = si[ao + min(ia, SEGK - 1)]; ia++; }
                else       { ov[o] = vb; oi[o] = si[bo + min(ib, SEGK - 1)]; ib++; }
            }
            #pragma unroll
            for (int o = 0; o < SEGK; o++) { sv[ao + o] = ov[o]; si[ao + o] = oi[o]; }
        }
        __syncthreads();
    }

    if (tid == 0) {
        #pragma unroll
        for (int i = 0; i < SEGK; i++) {
            g_segv[(q * NSEG + seg) * SEGK + i] = sv[i];
            g_segi[(q * NSEG + seg) * SEGK + i] = si[i];
        }
    }
}

// ---------------- kernel 4: merge + exact fp32 rescore + final top-k ---------
__global__ __launch_bounds__(1024, 1)
void final_kernel(const float* __restrict__ bank, float* __restrict__ out,
                  int nrows, int k) {
    __shared__ float cv[NSEG * SEGK];
    __shared__ int   ci[NSEG * SEGK];
    __shared__ float sv[CAND];
    __shared__ int   sid[CAND];
    __shared__ float rv[CAND];
    const int q = blockIdx.x, tid = threadIdx.x;
    const int lane = tid & 31, warp = tid >> 5;

    if (tid < NSEG * SEGK) {
        cv[tid] = g_segv[q * NSEG * SEGK + tid];
        ci[tid] = g_segi[q * NSEG * SEGK + tid];
    }
    __syncthreads();

    if (tid == 0) {
        float bv[CAND]; int bi[CAND];
        #pragma unroll
        for (int i = 0; i < CAND; i++) { bv[i] = -3.4e38f; bi[i] = 0x7fffffff; }
        for (int i = 0; i < NSEG * SEGK; i++) {
            float v = cv[i]; int id = ci[i];
            float lv = bv[CAND - 1]; int li = bi[CAND - 1];
            if (v < lv || (v == lv && id >= li)) continue;
            int j = CAND - 1;
            while (j > 0 && (v > bv[j - 1] || (v == bv[j - 1] && id < bi[j - 1]))) {
                bv[j] = bv[j - 1]; bi[j] = bi[j - 1]; j--;
            }
            bv[j] = v; bi[j] = id;
        }
        #pragma unroll
        for (int i = 0; i < CAND; i++) { sv[i] = bv[i]; sid[i] = bi[i]; }
    }
    __syncthreads();

    // one warp per candidate (32 warps)
    {
        const int c = warp;
        const int id = sid[c];
        float val = -3.4e38f;
        if (id < nrows) {
            const float4* b4 = (const float4*)(bank + (long long)id * KDIM);
            const float4* q4 = (const float4*)(g_qn + q * KDIM);
            float dot = 0.f, ss = 0.f;
            #pragma unroll
            for (int i = 0; i < 6; i++) {
                float4 bb = b4[lane + i * 32];
                float4 qq = q4[lane + i * 32];
                dot = fmaf(qq.x, bb.x, fmaf(qq.y, bb.y, fmaf(qq.z, bb.z, fmaf(qq.w, bb.w, dot))));
                ss  = fmaf(bb.x, bb.x, fmaf(bb.y, bb.y, fmaf(bb.z, bb.z, fmaf(bb.w, bb.w, ss))));
            }
            #pragma unroll
            for (int o = 16; o; o >>= 1) {
                dot += __shfl_xor_sync(0xffffffffu, dot, o);
                ss  += __shfl_xor_sync(0xffffffffu, ss,  o);
            }
            val = dot / fmaxf(sqrtf(ss), 1e-12f);
        }
        if (lane == 0) rv[c] = val;
    }
    __syncthreads();

    if (tid == 0) {
        bool used[CAND];
        #pragma unroll
        for (int i = 0; i < CAND; i++) used[i] = false;
        for (int j = 0; j < k; j++) {
            int best = -1; float bvv = -3.4e38f;
            for (int i = 0; i < CAND; i++) {
                if (used[i]) continue;
                if (best < 0 || rv[i] > bvv ||
                    (rv[i] == bvv && sid[i] < sid[best])) { bvv = rv[i]; best = i; }
            }
            used[best] = true;
            out[q * k + j]          = bvv;
            out[NQ * k + q * k + j] = (float)sid[best];
        }
    }
}

// ---------------- launch -----------------------------------------------------
extern "C" void kernel_launch(void* const* d_in, const int* in_sizes, int n_in,
                              void* d_out, int out_size) {
    const float* query = (const float*)d_in[0];
    const float* bank  = (const float*)d_in[1];
    const int nrows = in_sizes[1] / KDIM;
    const int k = out_size / (2 * NQ);

    cudaFuncSetAttribute(score_kernel, cudaFuncAttributeMaxDynamicSharedMemorySize, SCORE_SMEM);

    norm_q_kernel<<<NQ, 256>>>(query);

    const int ntiles = (nrows + TILE_M - 1) / TILE_M;
    score_kernel<<<ntiles, 256, SCORE_SMEM>>>(bank, nrows);

    topk_kernel<<<dim3(NSEG, NQ), 256>>>(nrows);

    final_kernel<<<NQ, 1024>>>(bank, (float*)d_out, nrows, k);
}